// round 15
// baseline (speedup 1.0000x reference)
#include <cuda_runtime.h>
#include <cstdint>
#include <cstddef>

#define N_NODES 25
#define K_TOT   384
#define OUT_F   256
#define M_TOT   (8192 * 25)
#define NEG_BIG (-9e15f)
#define MAXNB   24
#define NCH     12

// ---- smem layout (per CTA) ----
#define STG_SZ   32768                  // per stage: A 16KB + B 16KB
#define OFF_A(i) ((i) * STG_SZ)
#define OFF_B(i) ((i) * STG_SZ + 16384)
#define OFF_HS   0                      // epilogue reuse: [64 cols][284 f] = 72704
#define HS_STRIDE 284
#define OFF_G    98304                  // 32 x 57 f = 7296 (beyond the 3 stages)
#define G_STRIDE 57
#define OFF_BIAS 105600                 // 64 f
#define DSMEM    105984

__device__ float    g_WTp[2 * OUT_F * K_TOT];   // [h][n][perm pos], rna * (1+2^-12)
__device__ float    g_diag[N_NODES];
__device__ int      g_nnzc[N_NODES];
__device__ uint32_t g_pk[N_NODES * MAXNB];

// ---------------- helpers ----------------
__device__ __forceinline__ uint32_t tf32b(float x) {
    uint32_t u; asm("cvt.rna.tf32.f32 %0, %1;" : "=r"(u) : "f"(x));
    return u;
}
__device__ __forceinline__ float tf32f(float x) { return __uint_as_float(tf32b(x)); }
__device__ __forceinline__ void cpa16(void* dst, const float* src) {
    uint32_t d = (uint32_t)__cvta_generic_to_shared(dst);
    asm volatile("cp.async.cg.shared.global [%0], [%1], 16;" :: "r"(d), "l"(src));
}
__device__ __forceinline__ void mma8u(float c[4], uint32_t a0, uint32_t a1,
                                      uint32_t a2, uint32_t a3,
                                      uint32_t b0, uint32_t b1) {
    asm volatile(
        "mma.sync.aligned.m16n8k8.row.col.f32.tf32.tf32.f32 "
        "{%0,%1,%2,%3}, {%4,%5,%6,%7}, {%8,%9}, {%0,%1,%2,%3};\n"
        : "+f"(c[0]), "+f"(c[1]), "+f"(c[2]), "+f"(c[3])
        : "r"(a0), "r"(a1), "r"(a2), "r"(a3), "r"(b0), "r"(b1));
}
#define COMMIT() asm volatile("cp.async.commit_group;")
#define WAITG1() asm volatile("cp.async.wait_group 1;")

// ================= setup ==================================================
__global__ void setup_kernel(const float* __restrict__ W,
                             const float* __restrict__ e,
                             const int*   __restrict__ rows,
                             const int*   __restrict__ cols,
                             int nnz) {
    // perm: pos = ch*32 + q*4 + e  <->
    //       k  = ch*32 + (q>>2)*16 + (e>>1)*8 + (q&3)*2 + (e&1)
    // Scale by (1+2^-12): cancels coherent bias of A-side hardware truncation.
    const float SC = 1.000244140625f;
    const int total = 2 * OUT_F * K_TOT;
    for (int i = blockIdx.x * blockDim.x + threadIdx.x; i < total;
         i += gridDim.x * blockDim.x) {
        int h   = i / (OUT_F * K_TOT);
        int rem = i - h * (OUT_F * K_TOT);
        int n   = rem / K_TOT;
        int pos = rem - n * K_TOT;
        int ch = pos >> 5, r5 = pos & 31;
        int q = r5 >> 2, ee = r5 & 3;
        int k = ch * 32 + ((q >> 2) << 4) + ((ee >> 1) << 3) + ((q & 3) << 1) + (ee & 1);
        g_WTp[i] = tf32f(W[h * (K_TOT * OUT_F) + k * OUT_F + n] * SC);
    }
    if (blockIdx.x == 0) {
        __shared__ float lg[N_NODES * N_NODES];
        int t = threadIdx.x;
        for (int i = t; i < N_NODES * N_NODES; i += blockDim.x) lg[i] = NEG_BIG;
        __syncthreads();
        for (int i = t; i < nnz; i += blockDim.x) lg[rows[i] * N_NODES + cols[i]] = e[i];
        __syncthreads();
        if (t < N_NODES) {
            float mx = -1e30f;
            #pragma unroll
            for (int n = 0; n < N_NODES; n++) mx = fmaxf(mx, lg[t * N_NODES + n]);
            float ex[N_NODES]; float s = 0.f;
            #pragma unroll
            for (int n = 0; n < N_NODES; n++) {
                ex[n] = expf(lg[t * N_NODES + n] - mx); s += ex[n];
            }
            float inv = 1.f / s;
            int cnt = 0;
            for (int n = 0; n < N_NODES; n++) {
                float a = ex[n] * inv;
                if (n == t) g_diag[t] = a;
                else if (lg[t * N_NODES + n] != NEG_BIG) {
                    g_pk[t * MAXNB + cnt] =
                        (__float_as_uint(a) & 0xFFFFFFE0u) | (uint32_t)n;
                    cnt++;
                }
            }
            g_nnzc[t] = cnt;
        }
    }
}

// ================= fused GEMM + output-mix MMA (128 thr, 2 CTA/SM) =======
__global__ void __launch_bounds__(128, 2)
fused_kernel(const float* __restrict__ nodev, const float* __restrict__ hid,
             const float* __restrict__ bias, float* __restrict__ out) {
    extern __shared__ char sm[];
    const int tid = threadIdx.x, wid = tid >> 5, lid = tid & 31;
    const int lr = lid >> 2, lc = lid & 3;
    const int wm = wid >> 1, wn = wid & 1;       // 2m x 2n warp grid
    const int rb = blockIdx.x >> 2, cb = blockIdx.x & 3;
    const int row0 = rb * 125;
    const int j0   = cb * 64;
    const int nrows = (M_TOT - row0 < 125) ? (M_TOT - row0) : 125;

    // ---- loaders (128 threads) ----
    auto fillX = [&](int s, int b) {
        const int k0 = s * 32;
        #pragma unroll
        for (int i = 0; i < 8; i++) {
            int idx = i * 128 + tid;
            int row = idx >> 3, g = idx & 7;
            int grow = row0 + row; if (grow >= M_TOT) grow = M_TOT - 1;
            const float* src = (k0 < 128)
                ? (nodev + (size_t)grow * 128 + k0 + g * 4)
                : (hid   + (size_t)grow * 256 + (k0 - 128) + g * 4);
            cpa16(sm + OFF_A(b) + row * 128 + ((g ^ (row & 7)) << 4), src);
        }
    };
    auto fillB = [&](int s, int b) {
        #pragma unroll
        for (int i = 0; i < 8; i++) {
            int idx = i * 128 + tid;
            int n = idx >> 3, g = idx & 7;       // n: 0..127 (64 W0 | 64 W1)
            int h = n >> 6, ncol = j0 + (n & 63);
            cpa16(sm + OFF_B(b) + n * 128 + ((g ^ (n & 7)) << 4),
                  g_WTp + (size_t)h * (OUT_F * K_TOT) + (size_t)ncol * K_TOT
                        + s * 32 + g * 4);
        }
    };

    // ---- prologue: 2 stages in flight, then G/bias ----
    fillX(0, 0); fillB(0, 0); COMMIT();
    fillX(1, 1); fillB(1, 1); COMMIT();

    float* G = (float*)(sm + OFF_G);
    for (int i = tid; i < 32 * G_STRIDE; i += 128) G[i] = 0.f;
    if (tid < 64) ((float*)(sm + OFF_BIAS))[tid] = bias[j0 + tid];
    __syncthreads();
    if (tid < N_NODES) {
        G[tid * G_STRIDE + tid] = tf32f(g_diag[tid]);
        int nn = g_nnzc[tid];
        for (int j = 0; j < nn; j++) {
            uint32_t u = g_pk[tid * MAXNB + j];
            G[tid * G_STRIDE + 25 + (u & 31u)] =
                tf32f(__uint_as_float(u & 0xFFFFFFE0u));
        }
    }

    float acc[4][8][4];
    #pragma unroll
    for (int a = 0; a < 4; a++)
        #pragma unroll
        for (int b = 0; b < 8; b++)
            #pragma unroll
            for (int c = 0; c < 4; c++) acc[a][b][c] = 0.f;

    const int aoff = (lc & 1) * 8;
    const int ag   = lc >> 1;

    // Hoisted invariant offsets (masks all reduce to lr since row%8 == lr):
    //   A load offset(mf, half, p, ks01) = (wm*64+mf*16+lr+half*8)*128
    //                                    + (((4p+2ks01+ag) ^ lr) << 4) + aoff
    //   B quad offset(nf, p) = (wn*64+nf*8+lr)*128 + (((4p+lc) ^ lr) << 4)
    // All are chunk-invariant; only the stage base changes (unrolled x3).

    // compute-body over one chunk with compile-time stage pointers
    auto chunk_body = [&](const char* Ab, const char* Bb) {
        #pragma unroll
        for (int p = 0; p < 2; p++) {
            float4 bq[8];
            #pragma unroll
            for (int nf = 0; nf < 8; nf++) {
                int n = wn * 64 + nf * 8 + lr;
                bq[nf] = *(const float4*)(Bb + n * 128 +
                          (((p * 4 + lc) ^ lr) << 4));
            }
            #pragma unroll
            for (int ks01 = 0; ks01 < 2; ks01++) {
                const int gsel = 4 * p + 2 * ks01 + ag;
                uint32_t a[4][4];
                #pragma unroll
                for (int mf = 0; mf < 4; mf++) {
                    int r0 = wm * 64 + mf * 16 + lr;
                    int r1 = r0 + 8;
                    uint2 v0 = *(const uint2*)(Ab + r0 * 128 +
                                ((gsel ^ lr) << 4) + aoff);
                    uint2 v1 = *(const uint2*)(Ab + r1 * 128 +
                                ((gsel ^ lr) << 4) + aoff);
                    a[mf][0] = v0.x;
                    a[mf][1] = v1.x;
                    a[mf][2] = v0.y;
                    a[mf][3] = v1.y;
                }
                #pragma unroll
                for (int nf = 0; nf < 8; nf++) {
                    uint32_t b0 = __float_as_uint(ks01 ? bq[nf].z : bq[nf].x);
                    uint32_t b1 = __float_as_uint(ks01 ? bq[nf].w : bq[nf].y);
                    #pragma unroll
                    for (int mf = 0; mf < 4; mf++)
                        mma8u(acc[mf][nf], a[mf][0], a[mf][1], a[mf][2], a[mf][3],
                              b0, b1);
                }
            }
        }
    };

    // ---- main loop: unrolled by 3 so stage bases are literals ----
    #pragma unroll 1
    for (int so = 0; so < NCH; so += 3) {
        // --- sub-chunk 0: stage 0 ---
        WAITG1();
        __syncthreads();
        if (so + 2 < NCH) { fillX(so + 2, 2); fillB(so + 2, 2); }
        COMMIT();
        chunk_body(sm + OFF_A(0), sm + OFF_B(0));

        // --- sub-chunk 1: stage 1 ---
        WAITG1();
        __syncthreads();
        if (so + 3 < NCH) { fillX(so + 3, 0); fillB(so + 3, 0); }
        COMMIT();
        chunk_body(sm + OFF_A(1), sm + OFF_B(1));

        // --- sub-chunk 2: stage 2 ---
        WAITG1();
        __syncthreads();
        if (so + 4 < NCH) { fillX(so + 4, 1); fillB(so + 4, 1); }
        COMMIT();
        chunk_body(sm + OFF_A(2), sm + OFF_B(2));
    }

    // ================= epilogue: out = G @ Hcat + bias ====================
    __syncthreads();    // tile smem dead -> Hs (G/bias are beyond the stages)

    for (int i = tid; i < 64 * 30; i += 128) {
        int col = i / 30, r = i % 30;
        int b = r / 6, kp = 50 + r % 6;
        *(float*)(sm + OFF_HS + (size_t)col * (HS_STRIDE * 4) + (b * 56 + kp) * 4) = 0.f;
    }
    __syncthreads();

    // stage acc -> Hs[col][krow]; wn selects H0/H1 krow band
    {
        #pragma unroll
        for (int mf = 0; mf < 4; mf++) {
            #pragma unroll
            for (int h = 0; h < 2; h++) {
                int R = wm * 64 + mf * 16 + lr + h * 8;
                if (R < 125) {
                    int b = (R * 1311) >> 15;
                    int node = R - b * 25;
                    int krow = b * 56 + node + wn * 25;
                    #pragma unroll
                    for (int nf = 0; nf < 8; nf++) {
                        int cl = nf * 8 + lc * 2;
                        *(float*)(sm + OFF_HS + (size_t)cl * (HS_STRIDE * 4) + krow * 4)
                            = tf32f(acc[mf][nf][h * 2]);
                        *(float*)(sm + OFF_HS + (size_t)(cl + 1) * (HS_STRIDE * 4) + krow * 4)
                            = tf32f(acc[mf][nf][h * 2 + 1]);
                    }
                }
            }
        }
    }
    __syncthreads();

    // mix MMAs: 40 tasks = 5 batches x 8 col-frags over 4 warps
    #pragma unroll 1
    for (int t = wid; t < 40; t += 4) {
        int b = t >> 3, nfc = t & 7;
        float macc[2][4];
        #pragma unroll
        for (int mf = 0; mf < 2; mf++)
            #pragma unroll
            for (int e = 0; e < 4; e++) macc[mf][e] = 0.f;

        #pragma unroll
        for (int kf = 0; kf < 7; kf++) {
            const char* hsb = sm + OFF_HS
                + (size_t)(nfc * 8 + lr) * (HS_STRIDE * 4)
                + (b * 56 + kf * 8 + lc) * 4;
            uint32_t bx = __float_as_uint(*(const float*)(hsb));
            uint32_t by = __float_as_uint(*(const float*)(hsb + 16));
            #pragma unroll
            for (int mf = 0; mf < 2; mf++) {
                int r = mf * 16 + lr;
                const float* g0 = G + r * G_STRIDE + kf * 8 + lc;
                const float* g1 = G + (r + 8) * G_STRIDE + kf * 8 + lc;
                mma8u(macc[mf],
                      __float_as_uint(g0[0]), __float_as_uint(g1[0]),
                      __float_as_uint(g0[4]), __float_as_uint(g1[4]),
                      bx, by);
            }
        }
        #pragma unroll
        for (int mf = 0; mf < 2; mf++) {
            #pragma unroll
            for (int h = 0; h < 2; h++) {
                int m = mf * 16 + lr + h * 8;
                int lrow = b * 25 + m;
                if (m < 25 && lrow < nrows) {
                    int cl = nfc * 8 + lc * 2;
                    float2 bv = *(const float2*)(sm + OFF_BIAS + cl * 4);
                    *(float2*)(out + ((size_t)row0 + lrow) * OUT_F + j0 + cl) =
                        make_float2(macc[mf][h * 2] + bv.x,
                                    macc[mf][h * 2 + 1] + bv.y);
                }
            }
        }
    }
}

// ================= launcher ==============================================
extern "C" void kernel_launch(void* const* d_in, const int* in_sizes, int n_in,
                              void* d_out, int out_size) {
    const float* nodev = (const float*)d_in[0];
    const float* hid   = (const float*)d_in[1];
    const float* W     = (const float*)d_in[2];
    const float* e     = (const float*)d_in[3];
    const float* bias  = (const float*)d_in[4];
    const int*   rows  = (const int*)d_in[5];
    const int*   cols  = (const int*)d_in[6];
    const int nnz = in_sizes[3];

    setup_kernel<<<64, 256>>>(W, e, rows, cols, nnz);

    cudaFuncSetAttribute(fused_kernel,
                         cudaFuncAttributeMaxDynamicSharedMemorySize, DSMEM);
    const int grid = ((M_TOT + 124) / 125) * 4;   // 6556
    fused_kernel<<<grid, 128, DSMEM>>>(nodev, hid, bias, (float*)d_out);
    (void)n_in; (void)out_size;
}

// round 16
// speedup vs baseline: 1.0675x; 1.0675x over previous
#include <cuda_runtime.h>
#include <cstdint>
#include <cstddef>

#define N_NODES 25
#define K_TOT   384
#define OUT_F   256
#define M_TOT   (8192 * 25)
#define NEG_BIG (-9e15f)
#define MAXNB   24
#define NCH     12

// ---- smem layout (per CTA) ----
#define STG_SZ   32768                  // per stage: A 16KB + B 16KB
#define OFF_A(i) ((i) * STG_SZ)
#define OFF_B(i) ((i) * STG_SZ + 16384)
#define OFF_HS   0                      // epilogue reuse: [64 cols][284 f] = 72704
#define HS_STRIDE 284
#define OFF_G    98304                  // 32 x 57 f (beyond the 3 stages)
#define G_STRIDE 57
#define OFF_BIAS 105600                 // 64 f
#define DSMEM    105984

__device__ float    g_WTp[2 * OUT_F * K_TOT];   // [h][n][perm pos], rna * (1+2^-12)
__device__ float    g_diag[N_NODES];
__device__ int      g_nnzc[N_NODES];
__device__ uint32_t g_pk[N_NODES * MAXNB];

// ---------------- helpers ----------------
__device__ __forceinline__ uint32_t tf32b(float x) {
    uint32_t u; asm("cvt.rna.tf32.f32 %0, %1;" : "=r"(u) : "f"(x));
    return u;
}
__device__ __forceinline__ float tf32f(float x) { return __uint_as_float(tf32b(x)); }
__device__ __forceinline__ void cpa16(void* dst, const float* src) {
    uint32_t d = (uint32_t)__cvta_generic_to_shared(dst);
    asm volatile("cp.async.cg.shared.global [%0], [%1], 16;" :: "r"(d), "l"(src));
}
// bit-reverse of 3-bit row index: conflict-free bank spread for fragment loads
__device__ __forceinline__ int rev3(int r) {
    return ((r & 1) << 2) | (r & 2) | ((r >> 2) & 1);
}
__device__ __forceinline__ void mma8u(float c[4], uint32_t a0, uint32_t a1,
                                      uint32_t a2, uint32_t a3,
                                      uint32_t b0, uint32_t b1) {
    asm volatile(
        "mma.sync.aligned.m16n8k8.row.col.f32.tf32.tf32.f32 "
        "{%0,%1,%2,%3}, {%4,%5,%6,%7}, {%8,%9}, {%0,%1,%2,%3};\n"
        : "+f"(c[0]), "+f"(c[1]), "+f"(c[2]), "+f"(c[3])
        : "r"(a0), "r"(a1), "r"(a2), "r"(a3), "r"(b0), "r"(b1));
}
#define COMMIT() asm volatile("cp.async.commit_group;")
#define WAITG1() asm volatile("cp.async.wait_group 1;")

// ================= setup ==================================================
__global__ void setup_kernel(const float* __restrict__ W,
                             const float* __restrict__ e,
                             const int*   __restrict__ rows,
                             const int*   __restrict__ cols,
                             int nnz) {
    // perm: pos = ch*32 + q*4 + e  <->
    //       k  = ch*32 + (q>>2)*16 + (e>>1)*8 + (q&3)*2 + (e&1)
    // Scale by (1+2^-12): cancels coherent bias of A-side hardware truncation.
    const float SC = 1.000244140625f;
    const int total = 2 * OUT_F * K_TOT;
    for (int i = blockIdx.x * blockDim.x + threadIdx.x; i < total;
         i += gridDim.x * blockDim.x) {
        int h   = i / (OUT_F * K_TOT);
        int rem = i - h * (OUT_F * K_TOT);
        int n   = rem / K_TOT;
        int pos = rem - n * K_TOT;
        int ch = pos >> 5, r5 = pos & 31;
        int q = r5 >> 2, ee = r5 & 3;
        int k = ch * 32 + ((q >> 2) << 4) + ((ee >> 1) << 3) + ((q & 3) << 1) + (ee & 1);
        g_WTp[i] = tf32f(W[h * (K_TOT * OUT_F) + k * OUT_F + n] * SC);
    }
    if (blockIdx.x == 0) {
        __shared__ float lg[N_NODES * N_NODES];
        int t = threadIdx.x;
        for (int i = t; i < N_NODES * N_NODES; i += blockDim.x) lg[i] = NEG_BIG;
        __syncthreads();
        for (int i = t; i < nnz; i += blockDim.x) lg[rows[i] * N_NODES + cols[i]] = e[i];
        __syncthreads();
        if (t < N_NODES) {
            float mx = -1e30f;
            #pragma unroll
            for (int n = 0; n < N_NODES; n++) mx = fmaxf(mx, lg[t * N_NODES + n]);
            float ex[N_NODES]; float s = 0.f;
            #pragma unroll
            for (int n = 0; n < N_NODES; n++) {
                ex[n] = expf(lg[t * N_NODES + n] - mx); s += ex[n];
            }
            float inv = 1.f / s;
            int cnt = 0;
            for (int n = 0; n < N_NODES; n++) {
                float a = ex[n] * inv;
                if (n == t) g_diag[t] = a;
                else if (lg[t * N_NODES + n] != NEG_BIG) {
                    g_pk[t * MAXNB + cnt] =
                        (__float_as_uint(a) & 0xFFFFFFE0u) | (uint32_t)n;
                    cnt++;
                }
            }
            g_nnzc[t] = cnt;
        }
    }
}

// ================= fused GEMM + output-mix MMA (128 thr, 2 CTA/SM) =======
__global__ void __launch_bounds__(128, 2)
fused_kernel(const float* __restrict__ nodev, const float* __restrict__ hid,
             const float* __restrict__ bias, float* __restrict__ out) {
    extern __shared__ char sm[];
    const int tid = threadIdx.x, wid = tid >> 5, lid = tid & 31;
    const int lr = lid >> 2, lc = lid & 3;
    const int flr = rev3(lr);                    // per-lane constant
    const int wm = wid >> 1, wn = wid & 1;       // 2m x 2n warp grid
    const int rb = blockIdx.x >> 2, cb = blockIdx.x & 3;
    const int row0 = rb * 125;
    const int j0   = cb * 64;
    const int nrows = (M_TOT - row0 < 125) ? (M_TOT - row0) : 125;

    // ---- loaders (128 threads) ----
    auto fillX = [&](int s, int b) {
        const int k0 = s * 32;
        #pragma unroll
        for (int i = 0; i < 8; i++) {
            int idx = i * 128 + tid;
            int row = idx >> 3, g = idx & 7;
            int grow = row0 + row; if (grow >= M_TOT) grow = M_TOT - 1;
            const float* src = (k0 < 128)
                ? (nodev + (size_t)grow * 128 + k0 + g * 4)
                : (hid   + (size_t)grow * 256 + (k0 - 128) + g * 4);
            cpa16(sm + OFF_A(b) + row * 128 + ((g ^ rev3(row & 7)) << 4), src);
        }
    };
    auto fillB = [&](int s, int b) {
        #pragma unroll
        for (int i = 0; i < 8; i++) {
            int idx = i * 128 + tid;
            int n = idx >> 3, g = idx & 7;       // n: 0..127 (64 W0 | 64 W1)
            int h = n >> 6, ncol = j0 + (n & 63);
            cpa16(sm + OFF_B(b) + n * 128 + ((g ^ rev3(n & 7)) << 4),
                  g_WTp + (size_t)h * (OUT_F * K_TOT) + (size_t)ncol * K_TOT
                        + s * 32 + g * 4);
        }
    };

    // ---- prologue: 2 stages in flight, then G/bias ----
    fillX(0, 0); fillB(0, 0); COMMIT();
    fillX(1, 1); fillB(1, 1); COMMIT();

    float* G = (float*)(sm + OFF_G);
    for (int i = tid; i < 32 * G_STRIDE; i += 128) G[i] = 0.f;
    if (tid < 64) ((float*)(sm + OFF_BIAS))[tid] = bias[j0 + tid];
    __syncthreads();
    if (tid < N_NODES) {
        G[tid * G_STRIDE + tid] = tf32f(g_diag[tid]);
        int nn = g_nnzc[tid];
        for (int j = 0; j < nn; j++) {
            uint32_t u = g_pk[tid * MAXNB + j];
            G[tid * G_STRIDE + 25 + (u & 31u)] =
                tf32f(__uint_as_float(u & 0xFFFFFFE0u));
        }
    }

    float acc[4][8][4];
    #pragma unroll
    for (int a = 0; a < 4; a++)
        #pragma unroll
        for (int b = 0; b < 8; b++)
            #pragma unroll
            for (int c = 0; c < 4; c++) acc[a][b][c] = 0.f;

    const int aoff = (lc & 1) * 8;
    const int ag   = lc >> 1;

    // ---- main loop: 3 stages, one barrier per chunk ----
    #pragma unroll 1
    for (int s = 0; s < NCH; s++) {
        const int buf = s % 3;
        WAITG1();
        __syncthreads();
        if (s + 2 < NCH) { fillX(s + 2, (s + 2) % 3); fillB(s + 2, (s + 2) % 3); }
        COMMIT();

        const char* Ab = sm + OFF_A(buf);
        const char* Bb = sm + OFF_B(buf);

        #pragma unroll
        for (int p = 0; p < 2; p++) {
            float4 bq[8];
            #pragma unroll
            for (int nf = 0; nf < 8; nf++) {
                int n = wn * 64 + nf * 8 + lr;
                bq[nf] = *(const float4*)(Bb + n * 128 +
                          (((p * 4 + lc) ^ flr) << 4));
            }
            #pragma unroll
            for (int ks01 = 0; ks01 < 2; ks01++) {
                const int ks = 2 * p + ks01;
                const int gsel = 2 * ks + ag;
                uint32_t a[4][4];
                #pragma unroll
                for (int mf = 0; mf < 4; mf++) {
                    int r0 = wm * 64 + mf * 16 + lr;
                    int r1 = r0 + 8;
                    uint2 v0 = *(const uint2*)(Ab + r0 * 128 +
                                ((gsel ^ flr) << 4) + aoff);
                    uint2 v1 = *(const uint2*)(Ab + r1 * 128 +
                                ((gsel ^ flr) << 4) + aoff);
                    a[mf][0] = v0.x;
                    a[mf][1] = v1.x;
                    a[mf][2] = v0.y;
                    a[mf][3] = v1.y;
                }
                #pragma unroll
                for (int nf = 0; nf < 8; nf++) {
                    uint32_t b0 = __float_as_uint(ks01 ? bq[nf].z : bq[nf].x);
                    uint32_t b1 = __float_as_uint(ks01 ? bq[nf].w : bq[nf].y);
                    #pragma unroll
                    for (int mf = 0; mf < 4; mf++)
                        mma8u(acc[mf][nf], a[mf][0], a[mf][1], a[mf][2], a[mf][3],
                              b0, b1);
                }
            }
        }
    }

    // ================= epilogue: out = G @ Hcat + bias ====================
    __syncthreads();    // tile smem dead -> Hs (G/bias are beyond the stages)

    for (int i = tid; i < 64 * 30; i += 128) {
        int col = i / 30, r = i % 30;
        int b = r / 6, kp = 50 + r % 6;
        *(float*)(sm + OFF_HS + (size_t)col * (HS_STRIDE * 4) + (b * 56 + kp) * 4) = 0.f;
    }
    __syncthreads();

    // stage acc -> Hs[col][krow]; wn selects H0/H1 krow band
    {
        #pragma unroll
        for (int mf = 0; mf < 4; mf++) {
            #pragma unroll
            for (int h = 0; h < 2; h++) {
                int R = wm * 64 + mf * 16 + lr + h * 8;
                if (R < 125) {
                    int b = (R * 1311) >> 15;
                    int node = R - b * 25;
                    int krow = b * 56 + node + wn * 25;
                    #pragma unroll
                    for (int nf = 0; nf < 8; nf++) {
                        int cl = nf * 8 + lc * 2;
                        *(float*)(sm + OFF_HS + (size_t)cl * (HS_STRIDE * 4) + krow * 4)
                            = tf32f(acc[mf][nf][h * 2]);
                        *(float*)(sm + OFF_HS + (size_t)(cl + 1) * (HS_STRIDE * 4) + krow * 4)
                            = tf32f(acc[mf][nf][h * 2 + 1]);
                    }
                }
            }
        }
    }
    __syncthreads();

    // mix MMAs: 40 tasks = 5 batches x 8 col-frags over 4 warps
    #pragma unroll 1
    for (int t = wid; t < 40; t += 4) {
        int b = t >> 3, nfc = t & 7;
        float macc[2][4];
        #pragma unroll
        for (int mf = 0; mf < 2; mf++)
            #pragma unroll
            for (int e = 0; e < 4; e++) macc[mf][e] = 0.f;

        #pragma unroll
        for (int kf = 0; kf < 7; kf++) {
            const char* hsb = sm + OFF_HS
                + (size_t)(nfc * 8 + lr) * (HS_STRIDE * 4)
                + (b * 56 + kf * 8 + lc) * 4;
            uint32_t bx = __float_as_uint(*(const float*)(hsb));
            uint32_t by = __float_as_uint(*(const float*)(hsb + 16));
            #pragma unroll
            for (int mf = 0; mf < 2; mf++) {
                int r = mf * 16 + lr;
                const float* g0 = G + r * G_STRIDE + kf * 8 + lc;
                const float* g1 = G + (r + 8) * G_STRIDE + kf * 8 + lc;
                mma8u(macc[mf],
                      __float_as_uint(g0[0]), __float_as_uint(g1[0]),
                      __float_as_uint(g0[4]), __float_as_uint(g1[4]),
                      bx, by);
            }
        }
        #pragma unroll
        for (int mf = 0; mf < 2; mf++) {
            #pragma unroll
            for (int h = 0; h < 2; h++) {
                int m = mf * 16 + lr + h * 8;
                int lrow = b * 25 + m;
                if (m < 25 && lrow < nrows) {
                    int cl = nfc * 8 + lc * 2;
                    float2 bv = *(const float2*)(sm + OFF_BIAS + cl * 4);
                    *(float2*)(out + ((size_t)row0 + lrow) * OUT_F + j0 + cl) =
                        make_float2(macc[mf][h * 2] + bv.x,
                                    macc[mf][h * 2 + 1] + bv.y);
                }
            }
        }
    }
}

// ================= launcher ==============================================
extern "C" void kernel_launch(void* const* d_in, const int* in_sizes, int n_in,
                              void* d_out, int out_size) {
    const float* nodev = (const float*)d_in[0];
    const float* hid   = (const float*)d_in[1];
    const float* W     = (const float*)d_in[2];
    const float* e     = (const float*)d_in[3];
    const float* bias  = (const float*)d_in[4];
    const int*   rows  = (const int*)d_in[5];
    const int*   cols  = (const int*)d_in[6];
    const int nnz = in_sizes[3];

    setup_kernel<<<64, 256>>>(W, e, rows, cols, nnz);

    cudaFuncSetAttribute(fused_kernel,
                         cudaFuncAttributeMaxDynamicSharedMemorySize, DSMEM);
    const int grid = ((M_TOT + 124) / 125) * 4;   // 6556
    fused_kernel<<<grid, 128, DSMEM>>>(nodev, hid, bias, (float*)d_out);
    (void)n_in; (void)out_size;
}